// round 17
// baseline (speedup 1.0000x reference)
#include <cuda_runtime.h>
#include <cstdint>

#define TPB 256
#define NLAYER 4
#define LN_EPS 1e-5f

typedef unsigned long long u64;

// Packed fp32-pair ops (Blackwell f32x2 pipe; ptxas never auto-fuses these).
__device__ __forceinline__ void fma2(u64& acc, u64 a, u64 w) {
    asm("fma.rn.f32x2 %0, %1, %2, %0;" : "+l"(acc) : "l"(a), "l"(w));
}
__device__ __forceinline__ u64 pack2(float v) {
    u64 r; asm("mov.b64 %0, {%1, %1};" : "=l"(r) : "f"(v)); return r;
}
__device__ __forceinline__ void add2(u64& a, u64 b) {
    asm("add.rn.f32x2 %0, %0, %1;" : "+l"(a) : "l"(b));
}

__device__ __forceinline__ uint32_t s2u(const void* p) {
    uint32_t a;
    asm("{ .reg .u64 t; cvta.to.shared.u64 t, %1; cvt.u32.u64 %0, t; }"
        : "=r"(a) : "l"(p));
    return a;
}

// Spin-wait on mbarrier phase 0 with acquire (we read TMA-written smem after).
__device__ __forceinline__ void mbar_wait0(uint32_t mb) {
    asm volatile(
        "{\n\t"
        ".reg .pred P;\n\t"
        "WAITLP%=:\n\t"
        "mbarrier.try_wait.parity.acquire.cta.shared::cta.b64 P, [%0], 0;\n\t"
        "@P bra WAITDN%=;\n\t"
        "bra WAITLP%=;\n\t"
        "WAITDN%=:\n\t"
        "}"
        :: "r"(mb) : "memory");
}

// Per-item mutable state, stride-36 rows (16B aligned). ~31.8 KB each.
struct __align__(16) ItemState {
    float xs[64][36];               // node features
    float Lij[16][36];              // line sums over k, PRE-SCALED by 1/12
    float Lik[16][36];              // line sums over j, PRE-SCALED by 1/12
    float Si[4][36];                // plane sums over (j,k), PRE-SCALED
    float Sj[4][36];                // plane sums over (i,k), PRE-SCALED
    float Sk[4][36];                // plane sums over (i,j), PRE-SCALED
    float AW[3][16][36];            // agg_r @ W_r
    float Hroot[64][36];            // x @ R + bias
};

// ~131 KB shared -> 1 block/SM; grid=128 on 148 SMs.
struct __align__(16) Smem {
    float R[NLAYER][32][32];        // conv_root   (TMA-staged, 16 KB)
    float W[NLAYER][3][32][32];     // conv_w      (TMA-staged, 48 KB, adjacent)
    float bias[NLAYER][32];
    float Wf[6][32];
    float bf[32], lng[32], lnb[32];
    ItemState it[2];                // both items processed by ALL threads
    alignas(8) u64 mbar;            // TMA completion barrier
};

__global__ __launch_bounds__(TPB, 1) void gnn_frame0_kernel(
    const float* __restrict__ xx, const float* __restrict__ ss,
    const float* __restrict__ W_f, const float* __restrict__ b_f,
    const float* __restrict__ conv_w, const float* __restrict__ conv_root,
    const float* __restrict__ conv_bias, const float* __restrict__ ln_g,
    const float* __restrict__ ln_b, float* __restrict__ out)
{
    extern __shared__ __align__(16) unsigned char smem_raw[];
    Smem* s = reinterpret_cast<Smem*>(smem_raw);
    const int t = threadIdx.x;
    const int item0 = blockIdx.x * 2;
    ItemState* it0 = &s->it[0];
    ItemState* it1 = &s->it[1];
    const uint32_t mb = s2u(&s->mbar);
    const float SC = 1.0f / 12.0f;

    // ---- async bulk staging of R+W (64KB, once per block / 2 items) ----
    if (t == 0) {
        asm volatile("mbarrier.init.shared.b64 [%0], %1;" :: "r"(mb), "r"(1) : "memory");
        asm volatile("fence.proxy.async.shared::cta;" ::: "memory");
        asm volatile("mbarrier.arrive.expect_tx.shared.b64 _, [%0], %1;"
                     :: "r"(mb), "r"(65536) : "memory");
        uint32_t dR = s2u(&s->R[0][0][0]);
        uint32_t dW = s2u(&s->W[0][0][0][0]);
        asm volatile(
            "cp.async.bulk.shared::cta.global.mbarrier::complete_tx::bytes [%0], [%1], %2, [%3];"
            :: "r"(dR), "l"(conv_root), "r"(16384), "r"(mb) : "memory");
        asm volatile(
            "cp.async.bulk.shared::cta.global.mbarrier::complete_tx::bytes [%0], [%1], %2, [%3];"
            :: "r"(dW), "l"(conv_w), "r"(49152), "r"(mb) : "memory");
    }
    // small tables: scalar loads, concurrent with the bulk copy
    if (t >= 32 && t < 64) {
        reinterpret_cast<float4*>(&s->bias[0][0])[t - 32] =
            reinterpret_cast<const float4*>(conv_bias)[t - 32];
    } else if (t >= 64 && t < 112) {
        reinterpret_cast<float4*>(&s->Wf[0][0])[t - 64] =
            reinterpret_cast<const float4*>(W_f)[t - 64];
    } else if (t >= 112 && t < 144) {
        s->bf[t - 112] = b_f[t - 112];
    } else if (t >= 144 && t < 176) {
        s->lng[t - 144] = ln_g[t - 144];
    } else if (t >= 176 && t < 208) {
        s->lnb[t - 176] = ln_b[t - 176];
    }

    // thread -> (node, 8-channel group) for init / combine phases
    const int nd  = t >> 2;
    const int ch0 = (t & 3) * 8;
    const int ii = nd >> 4, jj = (nd >> 2) & 3, kk = nd & 3;
    const int rij = (ii << 2) | jj;
    const int rik = (ii << 2) | kk;

    __syncthreads();   // small tables + mbarrier.init visible

    // ---- initial features for BOTH items ----
    {
        const float fi = ii * (1.0f / 3.0f);
        const float fj = jj * (1.0f / 3.0f);
        const float fk = kk * (1.0f / 3.0f);
        const float v0 = xx[item0 * 512 + nd];
        const float v1 = xx[(item0 + 1) * 512 + nd];
        const float m0 = ss[item0] * 0.125f;
        const float m1 = ss[item0 + 1] * 0.125f;
        #pragma unroll
        for (int q = 0; q < 8; q++) {
            int c = ch0 + q;
            float base = s->bf[c] + fi * s->Wf[0][c] + fj * s->Wf[1][c]
                       + fk * s->Wf[2][c];
            it0->xs[nd][c] = base + v0 * s->Wf[4][c] + m0 * s->Wf[5][c];
            it1->xs[nd][c] = base + v1 * s->Wf[4][c] + m1 * s->Wf[5][c];
        }
    }
    __syncthreads();

    // ---- Phase-B mapping: 56 row-pairs x 4 eighth-slices = 224 threads ----
    const int pairIdx = t >> 2;
    const int cc8 = (t & 3) * 8;
    int pOffP = 0, pOffL0 = 0, pOffL1 = 0, dOff0 = 0, dOff1 = 0;
    int  wOff = 0;
    bool isRoot = false;
    if (t < 224) {
        int rowA, rowB;
        if (pairIdx < 24) {
            int r = pairIdx >> 3, tt = pairIdx & 7;
            wOff = r * 1024;
            if (r == 0) {
                rowA = 2 * tt; rowB = 2 * tt + 1;
                pOffP  = (int)(it0->Si[tt >> 1] - (float*)it0);
                pOffL0 = (int)(it0->Lij[rowA] - (float*)it0);
                pOffL1 = (int)(it0->Lij[rowB] - (float*)it0);
            } else if (r == 1) {
                int j = tt & 3, i0 = (tt >> 2) * 2;
                rowA = i0 * 4 + j; rowB = (i0 + 1) * 4 + j;
                pOffP  = (int)(it0->Sj[j] - (float*)it0);
                pOffL0 = (int)(it0->Lij[rowA] - (float*)it0);
                pOffL1 = (int)(it0->Lij[rowB] - (float*)it0);
            } else {
                int k = tt & 3, i0 = (tt >> 2) * 2;
                rowA = i0 * 4 + k; rowB = (i0 + 1) * 4 + k;
                pOffP  = (int)(it0->Sk[k] - (float*)it0);
                pOffL0 = (int)(it0->Lik[rowA] - (float*)it0);
                pOffL1 = (int)(it0->Lik[rowB] - (float*)it0);
            }
            dOff0 = (int)(&it0->AW[r][rowA][cc8] - (float*)it0);
            dOff1 = (int)(&it0->AW[r][rowB][cc8] - (float*)it0);
        } else {
            int n0 = (pairIdx - 24) * 2;
            pOffL0 = (int)(it0->xs[n0] - (float*)it0);
            pOffL1 = (int)(it0->xs[n0 + 1] - (float*)it0);
            dOff0 = (int)(&it0->Hroot[n0][cc8] - (float*)it0);
            dOff1 = (int)(&it0->Hroot[n0 + 1][cc8] - (float*)it0);
            isRoot = true;
        }
    }
    const float* b0f = (const float*)it0;
    const float* b1f = (const float*)it1;

    // ---- 4 R-GCN layers; all phases process BOTH items per thread ----
    for (int l = 0; l < NLAYER; l++) {
        // Phase A (vectorized): line sums = 512 float4 units (2/thread),
        // plane sums = 192 float4 units (t<192). All outputs pre-scaled 1/12.
        #pragma unroll
        for (int u = t; u < 512; u += TPB) {
            int cg  = (u & 7) * 4;
            int row = (u >> 3) & 15;
            int arr = (u >> 7) & 1;
            ItemState* itc = (u >> 8) ? it1 : it0;
            float4 r0, r1, r2, r3;
            if (arr == 0) {
                r0 = *reinterpret_cast<const float4*>(&itc->xs[row * 4 + 0][cg]);
                r1 = *reinterpret_cast<const float4*>(&itc->xs[row * 4 + 1][cg]);
                r2 = *reinterpret_cast<const float4*>(&itc->xs[row * 4 + 2][cg]);
                r3 = *reinterpret_cast<const float4*>(&itc->xs[row * 4 + 3][cg]);
            } else {
                int base = (row >> 2) * 16 + (row & 3);
                r0 = *reinterpret_cast<const float4*>(&itc->xs[base + 0][cg]);
                r1 = *reinterpret_cast<const float4*>(&itc->xs[base + 4][cg]);
                r2 = *reinterpret_cast<const float4*>(&itc->xs[base + 8][cg]);
                r3 = *reinterpret_cast<const float4*>(&itc->xs[base + 12][cg]);
            }
            float4 sum;
            sum.x = (r0.x + r1.x + r2.x + r3.x) * SC;
            sum.y = (r0.y + r1.y + r2.y + r3.y) * SC;
            sum.z = (r0.z + r1.z + r2.z + r3.z) * SC;
            sum.w = (r0.w + r1.w + r2.w + r3.w) * SC;
            if (arr == 0)
                *reinterpret_cast<float4*>(&itc->Lij[row][cg]) = sum;
            else
                *reinterpret_cast<float4*>(&itc->Lik[row][cg]) = sum;
        }
        if (t < 192) {
            int v = (t >= 96) ? (t - 96) : t;
            ItemState* itc = (t >= 96) ? it1 : it0;
            int cg  = (v & 7) * 4;
            int idx = (v >> 3) & 3;
            int arr = v >> 5;                 // 0=Si, 1=Sj, 2=Sk
            float4 acc = make_float4(0.f, 0.f, 0.f, 0.f);
            #pragma unroll
            for (int m = 0; m < 16; m++) {
                int node;
                if (arr == 0)       node = idx * 16 + m;
                else if (arr == 1)  node = (m >> 2) * 16 + idx * 4 + (m & 3);
                else                node = (m >> 2) * 16 + (m & 3) * 4 + idx;
                float4 r = *reinterpret_cast<const float4*>(&itc->xs[node][cg]);
                acc.x += r.x; acc.y += r.y; acc.z += r.z; acc.w += r.w;
            }
            acc.x *= SC; acc.y *= SC; acc.z *= SC; acc.w *= SC;
            float4* dst = (arr == 0) ? reinterpret_cast<float4*>(&itc->Si[idx][cg])
                        : (arr == 1) ? reinterpret_cast<float4*>(&itc->Sj[idx][cg])
                                     : reinterpret_cast<float4*>(&itc->Sk[idx][cg]);
            *dst = acc;
        }
        __syncthreads();

        // Phase B: weights loaded ONCE feed both items (16 FFMA2 chains).
        if (t < 224) {
            if (l == 0) mbar_wait0(mb);   // first weight use: join the TMA
            u64 xA0[4] = {0,0,0,0}, xB0[4] = {0,0,0,0};   // item0 rows A,B
            u64 xA1[4] = {0,0,0,0}, xB1[4] = {0,0,0,0};   // item1 rows A,B
            if (!isRoot) {
                const float* Wl = &s->W[l][0][0][0] + wOff;
                #pragma unroll
                for (int k0 = 0; k0 < 32; k0 += 4) {
                    float4 p0 = *reinterpret_cast<const float4*>(b0f + pOffP + k0);
                    float4 q0 = *reinterpret_cast<const float4*>(b0f + pOffL0 + k0);
                    float4 q1 = *reinterpret_cast<const float4*>(b0f + pOffL1 + k0);
                    float4 p1 = *reinterpret_cast<const float4*>(b1f + pOffP + k0);
                    float4 r0 = *reinterpret_cast<const float4*>(b1f + pOffL0 + k0);
                    float4 r1 = *reinterpret_cast<const float4*>(b1f + pOffL1 + k0);
                    #pragma unroll
                    for (int kq = 0; kq < 4; kq++) {
                        const ulonglong2* w2 =
                            reinterpret_cast<const ulonglong2*>(Wl + (k0 + kq) * 32 + cc8);
                        ulonglong2 wA = w2[0], wB = w2[1];
                        float pv0 = (&p0.x)[kq], pv1 = (&p1.x)[kq];
                        u64 aA0 = pack2(pv0 - (&q0.x)[kq]);
                        u64 aB0 = pack2(pv0 - (&q1.x)[kq]);
                        u64 aA1 = pack2(pv1 - (&r0.x)[kq]);
                        u64 aB1 = pack2(pv1 - (&r1.x)[kq]);
                        fma2(xA0[0], aA0, wA.x); fma2(xA0[1], aA0, wA.y);
                        fma2(xA0[2], aA0, wB.x); fma2(xA0[3], aA0, wB.y);
                        fma2(xB0[0], aB0, wA.x); fma2(xB0[1], aB0, wA.y);
                        fma2(xB0[2], aB0, wB.x); fma2(xB0[3], aB0, wB.y);
                        fma2(xA1[0], aA1, wA.x); fma2(xA1[1], aA1, wA.y);
                        fma2(xA1[2], aA1, wB.x); fma2(xA1[3], aA1, wB.y);
                        fma2(xB1[0], aB1, wA.x); fma2(xB1[1], aB1, wA.y);
                        fma2(xB1[2], aB1, wB.x); fma2(xB1[3], aB1, wB.y);
                    }
                }
                // 1/12 already folded into the pre-scaled sums.
            } else {
                const float* Wl = &s->R[l][0][0];
                #pragma unroll
                for (int k0 = 0; k0 < 32; k0 += 4) {
                    float4 q0 = *reinterpret_cast<const float4*>(b0f + pOffL0 + k0);
                    float4 q1 = *reinterpret_cast<const float4*>(b0f + pOffL1 + k0);
                    float4 r0 = *reinterpret_cast<const float4*>(b1f + pOffL0 + k0);
                    float4 r1 = *reinterpret_cast<const float4*>(b1f + pOffL1 + k0);
                    #pragma unroll
                    for (int kq = 0; kq < 4; kq++) {
                        const ulonglong2* w2 =
                            reinterpret_cast<const ulonglong2*>(Wl + (k0 + kq) * 32 + cc8);
                        ulonglong2 wA = w2[0], wB = w2[1];
                        u64 aA0 = pack2((&q0.x)[kq]);
                        u64 aB0 = pack2((&q1.x)[kq]);
                        u64 aA1 = pack2((&r0.x)[kq]);
                        u64 aB1 = pack2((&r1.x)[kq]);
                        fma2(xA0[0], aA0, wA.x); fma2(xA0[1], aA0, wA.y);
                        fma2(xA0[2], aA0, wB.x); fma2(xA0[3], aA0, wB.y);
                        fma2(xB0[0], aB0, wA.x); fma2(xB0[1], aB0, wA.y);
                        fma2(xB0[2], aB0, wB.x); fma2(xB0[3], aB0, wB.y);
                        fma2(xA1[0], aA1, wA.x); fma2(xA1[1], aA1, wA.y);
                        fma2(xA1[2], aA1, wB.x); fma2(xA1[3], aA1, wB.y);
                        fma2(xB1[0], aB1, wA.x); fma2(xB1[1], aB1, wA.y);
                        fma2(xB1[2], aB1, wB.x); fma2(xB1[3], aB1, wB.y);
                    }
                }
                const ulonglong2* bb =
                    reinterpret_cast<const ulonglong2*>(&s->bias[l][cc8]);
                ulonglong2 bA = bb[0], bB = bb[1];
                add2(xA0[0], bA.x); add2(xA0[1], bA.y);
                add2(xA0[2], bB.x); add2(xA0[3], bB.y);
                add2(xB0[0], bA.x); add2(xB0[1], bA.y);
                add2(xB0[2], bB.x); add2(xB0[3], bB.y);
                add2(xA1[0], bA.x); add2(xA1[1], bA.y);
                add2(xA1[2], bB.x); add2(xA1[3], bB.y);
                add2(xB1[0], bA.x); add2(xB1[1], bA.y);
                add2(xB1[2], bB.x); add2(xB1[3], bB.y);
            }
            ulonglong2* dA0 = reinterpret_cast<ulonglong2*>((float*)it0 + dOff0);
            dA0[0] = make_ulonglong2(xA0[0], xA0[1]);
            dA0[1] = make_ulonglong2(xA0[2], xA0[3]);
            ulonglong2* dB0 = reinterpret_cast<ulonglong2*>((float*)it0 + dOff1);
            dB0[0] = make_ulonglong2(xB0[0], xB0[1]);
            dB0[1] = make_ulonglong2(xB0[2], xB0[3]);
            ulonglong2* dA1 = reinterpret_cast<ulonglong2*>((float*)it1 + dOff0);
            dA1[0] = make_ulonglong2(xA1[0], xA1[1]);
            dA1[1] = make_ulonglong2(xA1[2], xA1[3]);
            ulonglong2* dB1 = reinterpret_cast<ulonglong2*>((float*)it1 + dOff1);
            dB1[0] = make_ulonglong2(xB1[0], xB1[1]);
            dB1[1] = make_ulonglong2(xB1[2], xB1[3]);
        }
        __syncthreads();

        // Phase C: combine + ReLU + LayerNorm for both items.
        {
            const float4* g4 = reinterpret_cast<const float4*>(&s->lng[ch0]);
            const float4* n4 = reinterpret_cast<const float4*>(&s->lnb[ch0]);
            float4 g0 = g4[0], g1 = g4[1], N0 = n4[0], N1 = n4[1];
            #pragma unroll
            for (int g2 = 0; g2 < 2; g2++) {
                ItemState* itc = (g2 == 0) ? it0 : it1;
                float h[8];
                const float4* a0 = reinterpret_cast<const float4*>(&itc->AW[0][rij][ch0]);
                const float4* a1 = reinterpret_cast<const float4*>(&itc->AW[1][rij][ch0]);
                const float4* a2 = reinterpret_cast<const float4*>(&itc->AW[2][rik][ch0]);
                const float4* hr = reinterpret_cast<const float4*>(&itc->Hroot[nd][ch0]);
                #pragma unroll
                for (int q4 = 0; q4 < 2; q4++) {
                    float4 v0 = a0[q4], v1 = a1[q4], v2 = a2[q4], vr = hr[q4];
                    h[q4 * 4 + 0] = v0.x + v1.x + v2.x + vr.x;
                    h[q4 * 4 + 1] = v0.y + v1.y + v2.y + vr.y;
                    h[q4 * 4 + 2] = v0.z + v1.z + v2.z + vr.z;
                    h[q4 * 4 + 3] = v0.w + v1.w + v2.w + vr.w;
                }
                float ssum = 0.0f, sq = 0.0f;
                #pragma unroll
                for (int q = 0; q < 8; q++) {
                    h[q] = fmaxf(h[q], 0.0f);
                    ssum += h[q];
                    sq   += h[q] * h[q];
                }
                ssum += __shfl_xor_sync(0xffffffffu, ssum, 1);
                sq   += __shfl_xor_sync(0xffffffffu, sq, 1);
                ssum += __shfl_xor_sync(0xffffffffu, ssum, 2);
                sq   += __shfl_xor_sync(0xffffffffu, sq, 2);
                float mu  = ssum * (1.0f / 32.0f);
                float var = sq * (1.0f / 32.0f) - mu * mu;
                float rs  = rsqrtf(var + LN_EPS);
                float4 o0, o1;
                o0.x = (h[0] - mu) * rs * g0.x + N0.x;
                o0.y = (h[1] - mu) * rs * g0.y + N0.y;
                o0.z = (h[2] - mu) * rs * g0.z + N0.z;
                o0.w = (h[3] - mu) * rs * g0.w + N0.w;
                o1.x = (h[4] - mu) * rs * g1.x + N1.x;
                o1.y = (h[5] - mu) * rs * g1.y + N1.y;
                o1.z = (h[6] - mu) * rs * g1.z + N1.z;
                o1.w = (h[7] - mu) * rs * g1.w + N1.w;
                *reinterpret_cast<float4*>(&itc->xs[nd][ch0])     = o0;
                *reinterpret_cast<float4*>(&itc->xs[nd][ch0 + 4]) = o1;
            }
        }
        __syncthreads();
    }

    // ---- output epilogue (vectorized): 768 float4 units, 3/thread ----
    #pragma unroll
    for (int e = t; e < 768; e += TPB) {
        int itm = e / 384;
        int v   = e % 384;
        ItemState* itc = itm ? it1 : it0;
        int o  = v >> 3;
        int cg = (v & 7) * 4;
        int n0, n1, n2, n3;
        if (o < 16) {               // mean over i; o = j*4+k
            n0 = o; n1 = o + 16; n2 = o + 32; n3 = o + 48;
        } else if (o < 32) {        // mean over j; (o-16) = i*4+k
            int oo = o - 16; int base = (oo >> 2) * 16 + (oo & 3);
            n0 = base; n1 = base + 4; n2 = base + 8; n3 = base + 12;
        } else {                    // mean over k; (o-32) = i*4+j
            int oo = o - 32; int base = (oo >> 2) * 16 + (oo & 3) * 4;
            n0 = base; n1 = base + 1; n2 = base + 2; n3 = base + 3;
        }
        float4 r0 = *reinterpret_cast<const float4*>(&itc->xs[n0][cg]);
        float4 r1 = *reinterpret_cast<const float4*>(&itc->xs[n1][cg]);
        float4 r2 = *reinterpret_cast<const float4*>(&itc->xs[n2][cg]);
        float4 r3 = *reinterpret_cast<const float4*>(&itc->xs[n3][cg]);
        float4 res;
        res.x = (r0.x + r1.x + r2.x + r3.x) * 0.25f;
        res.y = (r0.y + r1.y + r2.y + r3.y) * 0.25f;
        res.z = (r0.z + r1.z + r2.z + r3.z) * 0.25f;
        res.w = (r0.w + r1.w + r2.w + r3.w) * 0.25f;
        *reinterpret_cast<float4*>(out + (size_t)(item0 + itm) * 1536 + o * 32 + cg) = res;
    }
}

extern "C" void kernel_launch(void* const* d_in, const int* in_sizes, int n_in,
                              void* d_out, int out_size) {
    const float* xx        = (const float*)d_in[0];
    const float* ss        = (const float*)d_in[1];
    const float* W_f       = (const float*)d_in[2];
    const float* b_f       = (const float*)d_in[3];
    const float* conv_w    = (const float*)d_in[4];
    const float* conv_root = (const float*)d_in[5];
    const float* conv_bias = (const float*)d_in[6];
    const float* ln_g      = (const float*)d_in[7];
    const float* ln_b      = (const float*)d_in[8];
    // d_in[9]/d_in[10] (src/dst) unused: aggregation has a closed form.

    const int B = in_sizes[1];          // 256 (even)

    cudaFuncSetAttribute(gnn_frame0_kernel,
                         cudaFuncAttributeMaxDynamicSharedMemorySize,
                         (int)sizeof(Smem));
    gnn_frame0_kernel<<<B / 2, TPB, sizeof(Smem)>>>(
        xx, ss, W_f, b_f, conv_w, conv_root, conv_bias, ln_g, ln_b,
        (float*)d_out);
}